// round 9
// baseline (speedup 1.0000x reference)
#include <cuda_runtime.h>
#include <cuda_bf16.h>
#include <math.h>

// ---------------- problem constants ----------------
#define MAXN 50000
#define MAXE 800000
#define D12  256

// ---------------- scratch (device globals, compile-time symbol refs only) ---
__device__ float g_bufA[MAXN * D12];
__device__ float g_bufB[MAXN * D12];
__device__ unsigned g_Wf[122880];          // precomputed bf16 B-fragment table
__device__ float g_als[MAXN * 4];
__device__ float g_ald[MAXN * 4];
__device__ float g_pcomb[MAXN * 128];      // [prow | pcol] combined
__device__ float g_wa[256];                // W1^T a1s/a1d per head
__device__ int g_deg[MAXN];
__device__ int g_off[MAXN + 1];
__device__ int g_cur[MAXN];
__device__ int g_csr[MAXE];

// fragment-table offsets (words)
#define FW1   0        // 32*256   = 8192   (nBn=4, K=32)
#define FW2   8192     // 256*256  = 65536  (nBn=4, K=256)
#define FW3   73728    // 256*128  = 32768  (nBn=2, K=256)
#define FPC   106496   // 128*128  = 16384  (nBn=2, K=128, block-structured mw1)

__device__ __forceinline__ unsigned pack_bf16(float lo, float hi) {
    unsigned d;
    asm("cvt.rn.bf16x2.f32 %0, %1, %2;" : "=r"(d) : "f"(hi), "f"(lo));
    return d;
}

// ---------------- one-time weight split into mma fragment layout -----------
// word index: fbase + tile*1024 + (ni*32 + lane)*4 + sub
//   tile = t*nBn + bn; sub: 0=b0 big, 1=b1 big, 2=b0 small, 3=b1 small
__global__ void wsplit_kernel(const float* W1, const float* W2, const float* W3,
                              const float* mw1) {
    int w = blockIdx.x * blockDim.x + threadIdx.x;
    if (w >= 122880) return;
    const float* src;
    int srcNc, nBn, rel, pcMode;
    if (w < 8192)        { src = W1;  srcNc = 256; nBn = 4; rel = w;          pcMode = 0; }
    else if (w < 73728)  { src = W2;  srcNc = 256; nBn = 4; rel = w - 8192;   pcMode = 0; }
    else if (w < 106496) { src = W3;  srcNc = 128; nBn = 2; rel = w - 73728;  pcMode = 0; }
    else                 { src = mw1; srcNc = 64;  nBn = 2; rel = w - 106496; pcMode = 1; }
    int tile = rel >> 10;
    int r = rel & 1023;
    int ni = r >> 7;
    int lane = (r >> 2) & 31;
    int sub = r & 3;
    int bs = sub >> 1, bw = sub & 1;
    int g = lane >> 2, tg = lane & 3;
    int bn = tile % nBn, t = tile / nBn;
    int P = tg + bw * 4;
    int colWithin = ni * 8 + g;
    int col = pcMode ? colWithin : (bn * 64 + colWithin);
    int k = (pcMode ? bn * 128 : 0) + t * 16 + 2 * P;
    float x0 = src[k * srcNc + col];
    float x1 = src[(k + 1) * srcNc + col];
    unsigned big = pack_bf16(x0, x1);
    float lo = __uint_as_float(big << 16);
    float hi = __uint_as_float(big & 0xffff0000u);
    unsigned sml = pack_bf16(x0 - lo, x1 - hi);
    g_Wf[w] = bs ? sml : big;
}

// ---------------- wa = per-channel (W1^T a1s / a1d) ----------------
__global__ void wa_kernel(const float* W1, const float* a1s, const float* a1d) {
    int tid = threadIdx.x;           // 256 threads, 1 block
    int c = tid >> 3;
    int q = tid & 7;
    int hd = q >> 1;
    int s = q & 1;
    const float* a = s ? a1d : a1s;
    float sum = 0.f;
    for (int i = 0; i < 64; i++)
        sum = fmaf(W1[c * 256 + hd * 64 + i], a[hd * 64 + i], sum);
    g_wa[tid] = sum;
}

// ---------------- layer-1 attention coefficients straight from x -----------
__global__ void al1x_kernel(const float* x, int N) {
    __shared__ float s_wa[256];
    int tid = threadIdx.x;           // 256 threads = 8 warps
    s_wa[tid] = g_wa[tid];
    __syncthreads();
    int n = blockIdx.x * 8 + (tid >> 5);
    int lane = tid & 31;
    if (n >= N) return;
    float xv = x[n * 32 + lane];
#pragma unroll
    for (int q = 0; q < 8; q++) {
        float p = xv * s_wa[lane * 8 + q];
#pragma unroll
        for (int o = 16; o; o >>= 1) p += __shfl_down_sync(0xffffffffu, p, o);
        if (lane == 0) {
            int hd = q >> 1;
            if (q & 1) g_ald[n * 4 + hd] = p;
            else       g_als[n * 4 + hd] = p;
        }
    }
}

// ---------------- CSR construction ----------------
__global__ void zero_deg_kernel(int n) {
    int i = blockIdx.x * blockDim.x + threadIdx.x;
    if (i < n) g_deg[i] = 0;
}

__global__ void hist_kernel(const int* ei, int E) {
    int i = blockIdx.x * blockDim.x + threadIdx.x;
    if (i < E) atomicAdd(&g_deg[ei[E + i]], 1);
}

__global__ void scan_kernel(int n) {
    __shared__ int sh[1024];
    __shared__ int s_carry;
    int tid = threadIdx.x;
    if (tid == 0) s_carry = 0;
    __syncthreads();
    for (int base = 0; base < n; base += 1024) {
        int v = (base + tid < n) ? g_deg[base + tid] : 0;
        sh[tid] = v;
        __syncthreads();
        for (int o = 1; o < 1024; o <<= 1) {
            int t2 = (tid >= o) ? sh[tid - o] : 0;
            __syncthreads();
            sh[tid] += t2;
            __syncthreads();
        }
        int incl = sh[tid];
        int c = s_carry;
        int total = sh[1023];
        if (base + tid < n) {
            int e = c + incl - v;
            g_off[base + tid] = e;
            g_cur[base + tid] = e;
        }
        __syncthreads();
        if (tid == 0) s_carry = c + total;
        __syncthreads();
    }
    if (tid == 0) g_off[n] = s_carry;
}

__global__ void scatter_kernel(const int* ei, int E) {
    int i = blockIdx.x * blockDim.x + threadIdx.x;
    if (i < E) {
        int d = ei[E + i];
        int s = ei[i];
        int p = atomicAdd(&g_cur[d], 1);
        g_csr[p] = s;
    }
}

// ---------------- layer-1 aggregation over raw x (128B/edge) ---------------
// reads x, g_als/g_ald/g_csr/g_off; writes g_bufB[n*128 + head*32 + c].
__global__ void agg1x_kernel(const float* x) {
    const int CHUNK = 32;
    int n = blockIdx.x;
    int t = threadIdx.x;              // 128 threads
    int head = t >> 5;
    int c = t & 31;
    __shared__ float sh_m[4];
    __shared__ float sh_iz[4];
    __shared__ float sh_ad[4];
    __shared__ float sh_alpha[CHUNK * 4];
    __shared__ int sh_src[CHUNK];

    int o0 = g_off[n];
    int deg = g_off[n + 1] - o0;
    int wid = t >> 5, lane = t & 31;

    // pass 1: per-head online softmax stats (warp per head)
    {
        int hd = wid;
        float adn = g_ald[n * 4 + hd];
        float m = -1e30f, s = 0.f;
        for (int j = lane; j <= deg; j += 32) {
            int src = (j < deg) ? g_csr[o0 + j] : n;
            float att = g_als[src * 4 + hd] + adn;
            att = att > 0.f ? att : 0.2f * att;
            float mn = fmaxf(m, att);
            s = s * __expf(m - mn) + __expf(att - mn);
            m = mn;
        }
#pragma unroll
        for (int o = 16; o; o >>= 1) {
            float m2 = __shfl_down_sync(0xffffffffu, m, o);
            float s2 = __shfl_down_sync(0xffffffffu, s, o);
            float mn = fmaxf(m, m2);
            s = s * __expf(m - mn) + s2 * __expf(m2 - mn);
            m = mn;
        }
        if (lane == 0) {
            sh_m[hd] = m;
            sh_iz[hd] = 1.0f / s;
            sh_ad[hd] = adn;
        }
    }
    __syncthreads();

    // pass 2: chunked alpha staging + weighted x accumulation
    float acc = 0.f;
    int total = deg + 1;
    for (int base = 0; base < total; base += CHUNK) {
        int cnt = min(CHUNK, total - base);
        {
            int j = t >> 2;
            int hd = t & 3;
            if (j < cnt) {
                int src = (base + j < deg) ? g_csr[o0 + base + j] : n;
                if (hd == 0) sh_src[j] = src;
                float att = g_als[src * 4 + hd] + sh_ad[hd];
                att = att > 0.f ? att : 0.2f * att;
                sh_alpha[j * 4 + hd] = __expf(att - sh_m[hd]) * sh_iz[hd];
            }
        }
        __syncthreads();
#pragma unroll 4
        for (int j = 0; j < cnt; j++) {
            float xv = x[sh_src[j] * 32 + c];
            acc = fmaf(xv, sh_alpha[j * 4 + head], acc);
        }
        __syncthreads();
    }
    g_bufB[(size_t)n * 128 + t] = acc;
}

// ---------------- 3-term bf16 tensor-core GEMM ----------------
// C[M,Nc] = A[M,:] @ B; B frags precomputed in g_Wf; A split in-kernel.
// Block 128(M) x 64(N), BK=16, 256 threads = 8 warps (4M x 2N).
// ASRC: 0=Aext, 1=g_bufB, 2=g_bufA. CSEL: 0=g_bufA, 1=g_bufB, 2=g_pcomb.
// EPI: 1 -> +bias, ELU. KOFF: 1 -> A col base = bn*32 (block-diagonal W1).

__device__ __forceinline__ void mma_bf16(float& d0, float& d1, float& d2, float& d3,
                                         unsigned a0, unsigned a1, unsigned a2, unsigned a3,
                                         unsigned b0, unsigned b1) {
    asm volatile(
        "mma.sync.aligned.m16n8k16.row.col.f32.bf16.bf16.f32 "
        "{%0,%1,%2,%3}, {%4,%5,%6,%7}, {%8,%9}, {%0,%1,%2,%3};"
        : "+f"(d0), "+f"(d1), "+f"(d2), "+f"(d3)
        : "r"(a0), "r"(a1), "r"(a2), "r"(a3), "r"(b0), "r"(b1));
}

template <int ASRC, int CSEL, int EPI, int KOFF>
__global__ void __launch_bounds__(256) gemm_bf_kernel(const float* Aext, const float* bias,
                                                      int fbase, int nBn, int M,
                                                      int lda, int kLen) {
    const float* A;
    if constexpr (ASRC == 0) A = Aext;
    else if constexpr (ASRC == 1) A = (const float*)g_bufB;
    else A = (const float*)g_bufA;
    float* C;
    if constexpr (CSEL == 0) C = g_bufA;
    else if constexpr (CSEL == 1) C = g_bufB;
    else C = g_pcomb;
    int Nc = nBn * 64;

    __shared__ unsigned sAb[1024];
    __shared__ unsigned sAs[1024];

    int tid = threadIdx.x;
    int bm = blockIdx.y * 128;
    int bn = blockIdx.x;
    int warpId = tid >> 5;
    int lane = tid & 31;
    int g = lane >> 2;
    int tg = lane & 3;
    int wCol = (warpId >> 2) * 32;
    int wTile0 = (warpId & 3) * 2;

    int aoff = KOFF ? bn * 32 : 0;

    int ar = tid >> 1;
    int khalf = tid & 1;
    int att = ar >> 4;
    int asub = ar & 15;
    int ahi = asub >> 3;
    int agg = asub & 7;

    float d[2][4][4];
#pragma unroll
    for (int mi = 0; mi < 2; mi++)
#pragma unroll
        for (int ni = 0; ni < 4; ni++)
#pragma unroll
            for (int q = 0; q < 4; q++) d[mi][ni][q] = 0.f;

    const unsigned* Wf = (const unsigned*)g_Wf;

    for (int k0 = 0; k0 < kLen; k0 += 16) {
        int t = k0 >> 4;
        // ---- stage A ----
        {
            float4 v0 = make_float4(0.f, 0.f, 0.f, 0.f);
            float4 v1 = make_float4(0.f, 0.f, 0.f, 0.f);
            if (bm + ar < M) {
                const float* p = A + (size_t)(bm + ar) * lda + aoff + k0 + khalf * 8;
                v0 = *(const float4*)p;
                v1 = *(const float4*)(p + 4);
            }
            float xs[8] = {v0.x, v0.y, v0.z, v0.w, v1.x, v1.y, v1.z, v1.w};
#pragma unroll
            for (int p2 = 0; p2 < 4; p2++) {
                int wsl = khalf * 2 + ahi;
                int slot = p2 ^ ((agg >> 1) & 3);
                int idx = att * 128 + (agg * 4 + slot) * 4 + wsl;
                unsigned big = pack_bf16(xs[2 * p2], xs[2 * p2 + 1]);
                float lo = __uint_as_float(big << 16);
                float hi = __uint_as_float(big & 0xffff0000u);
                sAb[idx] = big;
                sAs[idx] = pack_bf16(xs[2 * p2] - lo, xs[2 * p2 + 1] - hi);
            }
        }
        // ---- B fragments (coalesced, L2-hot) ----
        uint4 bfr[4];
        {
            const uint4* fb = (const uint4*)(Wf + fbase + (size_t)(t * nBn + bn) * 1024);
#pragma unroll
            for (int nj = 0; nj < 4; nj++)
                bfr[nj] = fb[((wCol >> 3) + nj) * 32 + lane];
        }
        __syncthreads();

        uint4 afb[2], afs[2];
#pragma unroll
        for (int mi = 0; mi < 2; mi++) {
            int base = (wTile0 + mi) * 128 + (g * 4 + (tg ^ ((g >> 1) & 3))) * 4;
            afb[mi] = *(const uint4*)&sAb[base];
            afs[mi] = *(const uint4*)&sAs[base];
        }
        __syncthreads();

#pragma unroll
        for (int ni = 0; ni < 4; ni++) {
            uint4 b = bfr[ni];
#pragma unroll
            for (int mi = 0; mi < 2; mi++) {
                float* dd = d[mi][ni];
                mma_bf16(dd[0], dd[1], dd[2], dd[3],
                         afb[mi].x, afb[mi].y, afb[mi].z, afb[mi].w, b.x, b.y);
                mma_bf16(dd[0], dd[1], dd[2], dd[3],
                         afb[mi].x, afb[mi].y, afb[mi].z, afb[mi].w, b.z, b.w);
                mma_bf16(dd[0], dd[1], dd[2], dd[3],
                         afs[mi].x, afs[mi].y, afs[mi].z, afs[mi].w, b.x, b.y);
            }
        }
    }

    // ---- epilogue ----
#pragma unroll
    for (int mi = 0; mi < 2; mi++) {
#pragma unroll
        for (int ni = 0; ni < 4; ni++) {
            int col = bn * 64 + wCol + ni * 8 + tg * 2;
            float v0 = d[mi][ni][0], v1 = d[mi][ni][1];
            float v2 = d[mi][ni][2], v3 = d[mi][ni][3];
            if constexpr (EPI == 1) {
                float b0 = bias[col], b1v = bias[col + 1];
                v0 += b0; v1 += b1v; v2 += b0; v3 += b1v;
                v0 = v0 > 0.f ? v0 : expm1f(v0);
                v1 = v1 > 0.f ? v1 : expm1f(v1);
                v2 = v2 > 0.f ? v2 : expm1f(v2);
                v3 = v3 > 0.f ? v3 : expm1f(v3);
            }
            int row0 = bm + (wTile0 + mi) * 16 + g;
            if (row0 < M)
                *(float2*)(C + (size_t)row0 * Nc + col) = make_float2(v0, v1);
            if (row0 + 8 < M)
                *(float2*)(C + (size_t)(row0 + 8) * Nc + col) = make_float2(v2, v3);
        }
    }
}

// ---------------- per-node attention coefficients (layers 2,3) -------------
// reads g_bufB (= GEMM output h); writes g_als/g_ald.
__global__ void al_kernel(const float* as, const float* ad, int N, int H, int C) {
    int gw = (blockIdx.x * blockDim.x + threadIdx.x) >> 5;
    int lane = threadIdx.x & 31;
    int n = gw / H;
    int hd = gw % H;
    if (n >= N) return;
    size_t base = (size_t)n * H * C + (size_t)hd * C;
    float s1 = 0.f, s2 = 0.f;
    for (int c = lane; c < C; c += 32) {
        float v = g_bufB[base + c];
        s1 = fmaf(v, as[hd * C + c], s1);
        s2 = fmaf(v, ad[hd * C + c], s2);
    }
#pragma unroll
    for (int o = 16; o; o >>= 1) {
        s1 += __shfl_down_sync(0xffffffffu, s1, o);
        s2 += __shfl_down_sync(0xffffffffu, s2, o);
    }
    if (lane == 0) {
        g_als[n * H + hd] = s1;
        g_ald[n * H + hd] = s2;
    }
}

// ---------------- GAT aggregation (layers 2,3): bufB -> bufA ---------------
template <int H, int C>
__global__ void agg_kernel(const float* bias, int applyElu) {
    const int D2 = H * C / 2;
    const int CHUNK = (H == 4) ? 32 : 64;
    int n = blockIdx.x;
    int t = threadIdx.x;
    __shared__ float sh_m[H];
    __shared__ float sh_iz[H];
    __shared__ float sh_ad[H];
    __shared__ float sh_alpha[CHUNK * H];
    __shared__ int sh_src[CHUNK];

    int o0 = g_off[n];
    int deg = g_off[n + 1] - o0;
    int wid = t >> 5, lane = t & 31;

    if (wid < H) {
        int hd = wid;
        float adn = g_ald[n * H + hd];
        float m = -1e30f, s = 0.f;
        for (int j = lane; j <= deg; j += 32) {
            int src = (j < deg) ? g_csr[o0 + j] : n;
            float att = g_als[src * H + hd] + adn;
            att = att > 0.f ? att : 0.2f * att;
            float mn = fmaxf(m, att);
            s = s * __expf(m - mn) + __expf(att - mn);
            m = mn;
        }
#pragma unroll
        for (int o = 16; o; o >>= 1) {
            float m2 = __shfl_down_sync(0xffffffffu, m, o);
            float s2 = __shfl_down_sync(0xffffffffu, s, o);
            float mn = fmaxf(m, m2);
            s = s * __expf(m - mn) + s2 * __expf(m2 - mn);
            m = mn;
        }
        if (lane == 0) {
            sh_m[hd] = m;
            sh_iz[hd] = 1.0f / s;
            sh_ad[hd] = adn;
        }
    }
    __syncthreads();

    int head = t / (C / 2);
    float2 acc = make_float2(0.f, 0.f);
    int total = deg + 1;
    const float2* h2 = (const float2*)g_bufB;
    for (int base = 0; base < total; base += CHUNK) {
        int cnt = min(CHUNK, total - base);
        {
            int j = t / H;
            int hd = t % H;
            if (j < cnt) {
                int src = (base + j < deg) ? g_csr[o0 + base + j] : n;
                if (hd == 0) sh_src[j] = src;
                float att = g_als[src * H + hd] + sh_ad[hd];
                att = att > 0.f ? att : 0.2f * att;
                sh_alpha[j * H + hd] = __expf(att - sh_m[hd]) * sh_iz[hd];
            }
        }
        __syncthreads();
#pragma unroll 4
        for (int j = 0; j < cnt; j++) {
            float2 v = h2[(size_t)sh_src[j] * D2 + t];
            float a = sh_alpha[j * H + head];
            acc.x = fmaf(v.x, a, acc.x);
            acc.y = fmaf(v.y, a, acc.y);
        }
        __syncthreads();
    }
    float rx = acc.x + bias[2 * t];
    float ry = acc.y + bias[2 * t + 1];
    if (applyElu) {
        rx = rx > 0.f ? rx : expm1f(rx);
        ry = ry > 0.f ? ry : expm1f(ry);
    }
    *(float2*)(g_bufA + (size_t)n * (2 * D2) + 2 * t) = make_float2(rx, ry);
}

// ---------------- edge MLP (warp per edge) ----------------
__global__ void __launch_bounds__(1024) edge_mlp_kernel(const int* ei, const float* ea,
                                const float* mw1, const float* mb1,
                                const float* mw2, const float* mb2,
                                const float* mw3, const float* mb3,
                                float* out, int E) {
    __shared__ float sw2[64 * 32];
    int tid = threadIdx.x;
    for (int i = tid; i < 64 * 32; i += 1024) sw2[i] = mw2[i];
    __syncthreads();

    int warp = (int)((blockIdx.x * (size_t)blockDim.x + tid) >> 5);
    int lane = tid & 31;
    if (warp >= E) return;
    int row = ei[warp];
    int col = ei[E + warp];
    float ea0 = ea[warp * 2 + 0];
    float ea1 = ea[warp * 2 + 1];

    int j0 = lane * 2;
    float2 pr = *(const float2*)(g_pcomb + (size_t)row * 128 + j0);
    float2 pc = *(const float2*)(g_pcomb + (size_t)col * 128 + 64 + j0);
    float o1a = pr.x + pc.x + ea0 * mw1[256 * 64 + j0] + ea1 * mw1[257 * 64 + j0] + mb1[j0];
    float o1b = pr.y + pc.y + ea0 * mw1[256 * 64 + j0 + 1] + ea1 * mw1[257 * 64 + j0 + 1] + mb1[j0 + 1];
    o1a = fmaxf(o1a, 0.f);
    o1b = fmaxf(o1b, 0.f);

    float acc = mb2[lane];
#pragma unroll
    for (int sl = 0; sl < 32; sl++) {
        float va = __shfl_sync(0xffffffffu, o1a, sl);
        float vb = __shfl_sync(0xffffffffu, o1b, sl);
        acc = fmaf(va, sw2[(2 * sl) * 32 + lane], acc);
        acc = fmaf(vb, sw2[(2 * sl + 1) * 32 + lane], acc);
    }
    acc = fmaxf(acc, 0.f);

    float v = acc * mw3[lane];
#pragma unroll
    for (int o = 16; o; o >>= 1) v += __shfl_down_sync(0xffffffffu, v, o);
    if (lane == 0) out[warp] = v + mb3[0];
}

// ---------------- launch ----------------
extern "C" void kernel_launch(void* const* d_in, const int* in_sizes, int n_in,
                              void* d_out, int out_size) {
    const float* x = (const float*)d_in[0];
    const int* ei = (const int*)d_in[1];
    const float* ea = (const float*)d_in[2];
    const float* W1 = (const float*)d_in[3];
    const float* a1s = (const float*)d_in[4];
    const float* a1d = (const float*)d_in[5];
    const float* b1 = (const float*)d_in[6];
    const float* W2 = (const float*)d_in[7];
    const float* a2s = (const float*)d_in[8];
    const float* a2d = (const float*)d_in[9];
    const float* b2 = (const float*)d_in[10];
    const float* W3 = (const float*)d_in[11];
    const float* a3s = (const float*)d_in[12];
    const float* a3d = (const float*)d_in[13];
    const float* b3 = (const float*)d_in[14];
    const float* mw1 = (const float*)d_in[15];
    const float* mb1 = (const float*)d_in[16];
    const float* mw2 = (const float*)d_in[17];
    const float* mb2 = (const float*)d_in[18];
    const float* mw3 = (const float*)d_in[19];
    const float* mb3 = (const float*)d_in[20];
    float* out = (float*)d_out;

    int N = in_sizes[0] / 32;
    int E = in_sizes[1] / 2;

    int mBlocks = (N + 127) / 128;
    dim3 g256(4, mBlocks);
    dim3 g128(2, mBlocks);
    int alBlocks4 = ((N * 4) * 32 + 255) / 256;
    int alBlocks1 = ((N * 1) * 32 + 255) / 256;

    // setup (independent of each other where possible)
    wa_kernel<<<1, 256>>>(W1, a1s, a1d);
    zero_deg_kernel<<<(N + 255) / 256, 256>>>(N);
    hist_kernel<<<(E + 255) / 256, 256>>>(ei, E);
    wsplit_kernel<<<480, 256>>>(W1, W2, W3, mw1);
    scan_kernel<<<1, 1024>>>(N);
    scatter_kernel<<<(E + 255) / 256, 256>>>(ei, E);

    // ---- layer 1 (agg-then-transform) ----
    al1x_kernel<<<(N + 7) / 8, 256>>>(x, N);
    agg1x_kernel<<<N, 128>>>(x);                               // x -> bufB (xagg)
    gemm_bf_kernel<1, 0, 1, 1><<<g256, 256>>>(x, b1, FW1, 4, N, 128, 32);  // -> bufA (x2)

    // ---- layer 2 ----
    gemm_bf_kernel<2, 1, 0, 0><<<g256, 256>>>(x, b1, FW2, 4, N, 256, 256); // bufA -> bufB (h2)
    al_kernel<<<alBlocks4, 256>>>(a2s, a2d, N, 4, 64);
    agg_kernel<4, 64><<<N, 128>>>(b2, 1);                      // bufB -> bufA (x3)

    // ---- layer 3 ----
    gemm_bf_kernel<2, 1, 0, 0><<<g128, 256>>>(x, b1, FW3, 2, N, 256, 256); // bufA -> bufB (h3)
    al_kernel<<<alBlocks1, 256>>>(a3s, a3d, N, 1, 128);
    agg_kernel<1, 128><<<N, 64>>>(b3, 0);                      // bufB -> bufA (h3agg)

    // ---- edge MLP precompute (single combined GEMM) ----
    gemm_bf_kernel<2, 2, 0, 0><<<g128, 256>>>(x, b1, FPC, 2, N, 128, 128); // bufA -> pcomb

    // ---- edge MLP ----
    int blocks = (E + 31) / 32;
    edge_mlp_kernel<<<blocks, 1024>>>(ei, ea, mw1, mb1, mw2, mb2, mw3, mb3, out, E);
}

// round 10
// speedup vs baseline: 1.5965x; 1.5965x over previous
#include <cuda_runtime.h>
#include <cuda_bf16.h>
#include <math.h>

// ---------------- problem constants ----------------
#define MAXN 50000
#define MAXE 800000
#define D12  256

// ---------------- scratch (device globals, compile-time symbol refs only) ---
__device__ float g_bufA[MAXN * D12];       // h (post-GEMM)
__device__ float g_bufB[MAXN * D12];       // aggregated output
__device__ unsigned g_Wf[122880];          // precomputed bf16 B-fragment table
__device__ float g_als[MAXN * 4];
__device__ float g_ald[MAXN * 4];
__device__ float g_pcomb[MAXN * 128];      // [prow | pcol] combined
__device__ int g_deg[MAXN];
__device__ int g_off[MAXN + 1];
__device__ int g_cur[MAXN];
__device__ int g_csr[MAXE];

// fragment-table offsets (words)
#define FW1   0        // 32*256   = 8192   (nBn=4, K=32)
#define FW2   8192     // 256*256  = 65536  (nBn=4, K=256)
#define FW3   73728    // 256*128  = 32768  (nBn=2, K=256)
#define FPC   106496   // 128*128  = 16384  (nBn=2, K=128, block-structured mw1)

__device__ __forceinline__ unsigned pack_bf16(float lo, float hi) {
    unsigned d;
    asm("cvt.rn.bf16x2.f32 %0, %1, %2;" : "=r"(d) : "f"(hi), "f"(lo));
    return d;
}

// ---------------- one-time weight split into mma fragment layout -----------
// word index: fbase + tile*1024 + (ni*32 + lane)*4 + sub
//   tile = t*nBn + bn; sub: 0=b0 big, 1=b1 big, 2=b0 small, 3=b1 small
__global__ void wsplit_kernel(const float* W1, const float* W2, const float* W3,
                              const float* mw1) {
    int w = blockIdx.x * blockDim.x + threadIdx.x;
    if (w >= 122880) return;
    const float* src;
    int srcNc, nBn, rel, pcMode;
    if (w < 8192)        { src = W1;  srcNc = 256; nBn = 4; rel = w;          pcMode = 0; }
    else if (w < 73728)  { src = W2;  srcNc = 256; nBn = 4; rel = w - 8192;   pcMode = 0; }
    else if (w < 106496) { src = W3;  srcNc = 128; nBn = 2; rel = w - 73728;  pcMode = 0; }
    else                 { src = mw1; srcNc = 64;  nBn = 2; rel = w - 106496; pcMode = 1; }
    int tile = rel >> 10;
    int r = rel & 1023;
    int ni = r >> 7;
    int lane = (r >> 2) & 31;
    int sub = r & 3;
    int bs = sub >> 1, bw = sub & 1;
    int g = lane >> 2, tg = lane & 3;
    int bn = tile % nBn, t = tile / nBn;
    int P = tg + bw * 4;
    int colWithin = ni * 8 + g;
    int col = pcMode ? colWithin : (bn * 64 + colWithin);
    int k = (pcMode ? bn * 128 : 0) + t * 16 + 2 * P;
    float x0 = src[k * srcNc + col];
    float x1 = src[(k + 1) * srcNc + col];
    unsigned big = pack_bf16(x0, x1);
    float lo = __uint_as_float(big << 16);
    float hi = __uint_as_float(big & 0xffff0000u);
    unsigned sml = pack_bf16(x0 - lo, x1 - hi);
    g_Wf[w] = bs ? sml : big;
}

// ---------------- CSR construction ----------------
__global__ void zero_deg_kernel(int n) {
    int i = blockIdx.x * blockDim.x + threadIdx.x;
    if (i < n) g_deg[i] = 0;
}

__global__ void hist_kernel(const int* ei, int E) {
    int i = blockIdx.x * blockDim.x + threadIdx.x;
    if (i < E) atomicAdd(&g_deg[ei[E + i]], 1);
}

__global__ void scan_kernel(int n) {
    __shared__ int sh[1024];
    __shared__ int s_carry;
    int tid = threadIdx.x;
    if (tid == 0) s_carry = 0;
    __syncthreads();
    for (int base = 0; base < n; base += 1024) {
        int v = (base + tid < n) ? g_deg[base + tid] : 0;
        sh[tid] = v;
        __syncthreads();
        for (int o = 1; o < 1024; o <<= 1) {
            int t2 = (tid >= o) ? sh[tid - o] : 0;
            __syncthreads();
            sh[tid] += t2;
            __syncthreads();
        }
        int incl = sh[tid];
        int c = s_carry;
        int total = sh[1023];
        if (base + tid < n) {
            int e = c + incl - v;
            g_off[base + tid] = e;
            g_cur[base + tid] = e;
        }
        __syncthreads();
        if (tid == 0) s_carry = c + total;
        __syncthreads();
    }
    if (tid == 0) g_off[n] = s_carry;
}

__global__ void scatter_kernel(const int* ei, int E) {
    int i = blockIdx.x * blockDim.x + threadIdx.x;
    if (i < E) {
        int d = ei[E + i];
        int s = ei[i];
        int p = atomicAdd(&g_cur[d], 1);
        g_csr[p] = s;
    }
}

// ---------------- 3-term bf16 tensor-core GEMM (double-buffered A) ---------
// C[M,Nc] = A[M,K] @ B[K,Nc]; B frags precomputed in g_Wf; A split in-kernel.
// Block 128(M) x 64(N), BK=16, 256 threads = 8 warps (4M x 2N).
// ASRC: 0 -> A = Aext; 1 -> A = g_bufB.
// CSEL: 0 -> g_bufA, 1 -> g_pcomb.

__device__ __forceinline__ void mma_bf16(float& d0, float& d1, float& d2, float& d3,
                                         unsigned a0, unsigned a1, unsigned a2, unsigned a3,
                                         unsigned b0, unsigned b1) {
    asm volatile(
        "mma.sync.aligned.m16n8k16.row.col.f32.bf16.bf16.f32 "
        "{%0,%1,%2,%3}, {%4,%5,%6,%7}, {%8,%9}, {%0,%1,%2,%3};"
        : "+f"(d0), "+f"(d1), "+f"(d2), "+f"(d3)
        : "r"(a0), "r"(a1), "r"(a2), "r"(a3), "r"(b0), "r"(b1));
}

template <int ASRC, int CSEL>
__global__ void __launch_bounds__(256) gemm_bf_kernel(const float* Aext, int fbase,
                                                      int nBn, int M, int K) {
    const float* A;
    if constexpr (ASRC == 0) A = Aext; else A = (const float*)g_bufB;
    float* C;
    if constexpr (CSEL == 0) C = g_bufA; else C = g_pcomb;
    int Nc = nBn * 64;

    __shared__ unsigned sAb[2][1024];
    __shared__ unsigned sAs[2][1024];

    int tid = threadIdx.x;
    int bm = blockIdx.y * 128;
    int bn = blockIdx.x;
    int warpId = tid >> 5;
    int lane = tid & 31;
    int g = lane >> 2;
    int tg = lane & 3;
    int wCol = (warpId >> 2) * 32;
    int wTile0 = (warpId & 3) * 2;

    int ar = tid >> 1;
    int khalf = tid & 1;
    int att = ar >> 4;
    int asub = ar & 15;
    int ahi = asub >> 3;
    int agg = asub & 7;

    float d[2][4][4];
#pragma unroll
    for (int mi = 0; mi < 2; mi++)
#pragma unroll
        for (int ni = 0; ni < 4; ni++)
#pragma unroll
            for (int q = 0; q < 4; q++) d[mi][ni][q] = 0.f;

    const unsigned* Wf = (const unsigned*)g_Wf;
    int p = 0;

    for (int k0 = 0; k0 < K; k0 += 16, p ^= 1) {
        int t = k0 >> 4;
        // ---- B fragments first (independent LDGs, overlap with A staging) ----
        uint4 bfr[4];
        {
            const uint4* fb = (const uint4*)(Wf + fbase + (size_t)(t * nBn + bn) * 1024);
#pragma unroll
            for (int nj = 0; nj < 4; nj++)
                bfr[nj] = fb[((wCol >> 3) + nj) * 32 + lane];
        }
        // ---- stage A into buffer p ----
        {
            float4 v0 = make_float4(0.f, 0.f, 0.f, 0.f);
            float4 v1 = make_float4(0.f, 0.f, 0.f, 0.f);
            if (bm + ar < M) {
                const float* pp = A + (size_t)(bm + ar) * K + k0 + khalf * 8;
                v0 = *(const float4*)pp;
                v1 = *(const float4*)(pp + 4);
            }
            float xs[8] = {v0.x, v0.y, v0.z, v0.w, v1.x, v1.y, v1.z, v1.w};
#pragma unroll
            for (int p2 = 0; p2 < 4; p2++) {
                int wsl = khalf * 2 + ahi;
                int slot = p2 ^ ((agg >> 1) & 3);
                int idx = att * 128 + (agg * 4 + slot) * 4 + wsl;
                unsigned big = pack_bf16(xs[2 * p2], xs[2 * p2 + 1]);
                float lo = __uint_as_float(big << 16);
                float hi = __uint_as_float(big & 0xffff0000u);
                sAb[p][idx] = big;
                sAs[p][idx] = pack_bf16(xs[2 * p2] - lo, xs[2 * p2 + 1] - hi);
            }
        }
        __syncthreads();

        // ---- A fragments: one LDS.128 per (tile, big/small) ----
        uint4 afb[2], afs[2];
#pragma unroll
        for (int mi = 0; mi < 2; mi++) {
            int base = (wTile0 + mi) * 128 + (g * 4 + (tg ^ ((g >> 1) & 3))) * 4;
            afb[mi] = *(const uint4*)&sAb[p][base];
            afs[mi] = *(const uint4*)&sAs[p][base];
        }
        // no second barrier: next iteration writes the OTHER buffer

        // ---- MMAs: Ab*Bb + Ab*Bs + As*Bb ----
#pragma unroll
        for (int ni = 0; ni < 4; ni++) {
            uint4 b = bfr[ni];
#pragma unroll
            for (int mi = 0; mi < 2; mi++) {
                float* dd = d[mi][ni];
                mma_bf16(dd[0], dd[1], dd[2], dd[3],
                         afb[mi].x, afb[mi].y, afb[mi].z, afb[mi].w, b.x, b.y);
                mma_bf16(dd[0], dd[1], dd[2], dd[3],
                         afb[mi].x, afb[mi].y, afb[mi].z, afb[mi].w, b.z, b.w);
                mma_bf16(dd[0], dd[1], dd[2], dd[3],
                         afs[mi].x, afs[mi].y, afs[mi].z, afs[mi].w, b.x, b.y);
            }
        }
    }

    // ---- epilogue (float2 stores) ----
#pragma unroll
    for (int mi = 0; mi < 2; mi++) {
#pragma unroll
        for (int ni = 0; ni < 4; ni++) {
            int row0 = bm + (wTile0 + mi) * 16 + g;
            int col = bn * 64 + wCol + ni * 8 + tg * 2;
            if (row0 < M)
                *(float2*)(C + (size_t)row0 * Nc + col) = make_float2(d[mi][ni][0], d[mi][ni][1]);
            if (row0 + 8 < M)
                *(float2*)(C + (size_t)(row0 + 8) * Nc + col) = make_float2(d[mi][ni][2], d[mi][ni][3]);
        }
    }
}

// ---------------- per-node attention coefficients ----------------
__global__ void al_kernel(const float* as, const float* ad, int N, int H, int C) {
    int gw = (blockIdx.x * blockDim.x + threadIdx.x) >> 5;
    int lane = threadIdx.x & 31;
    int n = gw / H;
    int hd = gw % H;
    if (n >= N) return;
    size_t base = (size_t)n * H * C + (size_t)hd * C;
    float s1 = 0.f, s2 = 0.f;
    for (int c = lane; c < C; c += 32) {
        float v = g_bufA[base + c];
        s1 = fmaf(v, as[hd * C + c], s1);
        s2 = fmaf(v, ad[hd * C + c], s2);
    }
#pragma unroll
    for (int o = 16; o; o >>= 1) {
        s1 += __shfl_down_sync(0xffffffffu, s1, o);
        s2 += __shfl_down_sync(0xffffffffu, s2, o);
    }
    if (lane == 0) {
        g_als[n * H + hd] = s1;
        g_ald[n * H + hd] = s2;
    }
}

// ---------------- GAT aggregation, float2-vectorized: bufA -> bufB ---------
template <int H, int C>
__global__ void agg_kernel(const float* bias, int applyElu) {
    const int D2 = H * C / 2;
    const int CHUNK = (H == 4) ? 32 : 64;
    int n = blockIdx.x;
    int t = threadIdx.x;
    __shared__ float sh_m[H];
    __shared__ float sh_iz[H];
    __shared__ float sh_ad[H];
    __shared__ float sh_alpha[CHUNK * H];
    __shared__ int sh_src[CHUNK];

    int o0 = g_off[n];
    int deg = g_off[n + 1] - o0;
    int wid = t >> 5, lane = t & 31;

    if (wid < H) {
        int hd = wid;
        float adn = g_ald[n * H + hd];
        float m = -1e30f, s = 0.f;
        for (int j = lane; j <= deg; j += 32) {
            int src = (j < deg) ? g_csr[o0 + j] : n;
            float att = g_als[src * H + hd] + adn;
            att = att > 0.f ? att : 0.2f * att;
            float mn = fmaxf(m, att);
            s = s * __expf(m - mn) + __expf(att - mn);
            m = mn;
        }
#pragma unroll
        for (int o = 16; o; o >>= 1) {
            float m2 = __shfl_down_sync(0xffffffffu, m, o);
            float s2 = __shfl_down_sync(0xffffffffu, s, o);
            float mn = fmaxf(m, m2);
            s = s * __expf(m - mn) + s2 * __expf(m2 - mn);
            m = mn;
        }
        if (lane == 0) {
            sh_m[hd] = m;
            sh_iz[hd] = 1.0f / s;
            sh_ad[hd] = adn;
        }
    }
    __syncthreads();

    int head = t / (C / 2);
    float2 acc = make_float2(0.f, 0.f);
    int total = deg + 1;
    const float2* h2 = (const float2*)g_bufA;
    for (int base = 0; base < total; base += CHUNK) {
        int cnt = min(CHUNK, total - base);
        {
            int j = t / H;
            int hd = t % H;
            if (j < cnt) {
                int src = (base + j < deg) ? g_csr[o0 + base + j] : n;
                if (hd == 0) sh_src[j] = src;
                float att = g_als[src * H + hd] + sh_ad[hd];
                att = att > 0.f ? att : 0.2f * att;
                sh_alpha[j * H + hd] = __expf(att - sh_m[hd]) * sh_iz[hd];
            }
        }
        __syncthreads();
#pragma unroll 4
        for (int j = 0; j < cnt; j++) {
            float2 v = h2[(size_t)sh_src[j] * D2 + t];
            float a = sh_alpha[j * H + head];
            acc.x = fmaf(v.x, a, acc.x);
            acc.y = fmaf(v.y, a, acc.y);
        }
        __syncthreads();
    }
    float rx = acc.x + bias[2 * t];
    float ry = acc.y + bias[2 * t + 1];
    if (applyElu) {
        rx = rx > 0.f ? rx : expm1f(rx);
        ry = ry > 0.f ? ry : expm1f(ry);
    }
    *(float2*)(g_bufB + (size_t)n * (2 * D2) + 2 * t) = make_float2(rx, ry);
}

// ---------------- edge MLP (warp per edge) ----------------
__global__ void __launch_bounds__(1024) edge_mlp_kernel(const int* ei, const float* ea,
                                const float* mw1, const float* mb1,
                                const float* mw2, const float* mb2,
                                const float* mw3, const float* mb3,
                                float* out, int E) {
    __shared__ float sw2[64 * 32];
    int tid = threadIdx.x;
    for (int i = tid; i < 64 * 32; i += 1024) sw2[i] = mw2[i];
    __syncthreads();

    int warp = (int)((blockIdx.x * (size_t)blockDim.x + tid) >> 5);
    int lane = tid & 31;
    if (warp >= E) return;
    int row = ei[warp];
    int col = ei[E + warp];
    float ea0 = ea[warp * 2 + 0];
    float ea1 = ea[warp * 2 + 1];

    int j0 = lane * 2;
    float2 pr = *(const float2*)(g_pcomb + (size_t)row * 128 + j0);
    float2 pc = *(const float2*)(g_pcomb + (size_t)col * 128 + 64 + j0);
    float o1a = pr.x + pc.x + ea0 * mw1[256 * 64 + j0] + ea1 * mw1[257 * 64 + j0] + mb1[j0];
    float o1b = pr.y + pc.y + ea0 * mw1[256 * 64 + j0 + 1] + ea1 * mw1[257 * 64 + j0 + 1] + mb1[j0 + 1];
    o1a = fmaxf(o1a, 0.f);
    o1b = fmaxf(o1b, 0.f);

    float acc = mb2[lane];
#pragma unroll
    for (int sl = 0; sl < 32; sl++) {
        float va = __shfl_sync(0xffffffffu, o1a, sl);
        float vb = __shfl_sync(0xffffffffu, o1b, sl);
        acc = fmaf(va, sw2[(2 * sl) * 32 + lane], acc);
        acc = fmaf(vb, sw2[(2 * sl + 1) * 32 + lane], acc);
    }
    acc = fmaxf(acc, 0.f);

    float v = acc * mw3[lane];
#pragma unroll
    for (int o = 16; o; o >>= 1) v += __shfl_down_sync(0xffffffffu, v, o);
    if (lane == 0) out[warp] = v + mb3[0];
}

// ---------------- launch ----------------
extern "C" void kernel_launch(void* const* d_in, const int* in_sizes, int n_in,
                              void* d_out, int out_size) {
    const float* x = (const float*)d_in[0];
    const int* ei = (const int*)d_in[1];
    const float* ea = (const float*)d_in[2];
    const float* W1 = (const float*)d_in[3];
    const float* a1s = (const float*)d_in[4];
    const float* a1d = (const float*)d_in[5];
    const float* b1 = (const float*)d_in[6];
    const float* W2 = (const float*)d_in[7];
    const float* a2s = (const float*)d_in[8];
    const float* a2d = (const float*)d_in[9];
    const float* b2 = (const float*)d_in[10];
    const float* W3 = (const float*)d_in[11];
    const float* a3s = (const float*)d_in[12];
    const float* a3d = (const float*)d_in[13];
    const float* b3 = (const float*)d_in[14];
    const float* mw1 = (const float*)d_in[15];
    const float* mb1 = (const float*)d_in[16];
    const float* mw2 = (const float*)d_in[17];
    const float* mb2 = (const float*)d_in[18];
    const float* mw3 = (const float*)d_in[19];
    const float* mb3 = (const float*)d_in[20];
    float* out = (float*)d_out;

    int N = in_sizes[0] / 32;
    int E = in_sizes[1] / 2;

    int mBlocks = (N + 127) / 128;
    dim3 g256(4, mBlocks);
    dim3 g128(2, mBlocks);
    int alBlocks4 = ((N * 4) * 32 + 255) / 256;
    int alBlocks1 = ((N * 1) * 32 + 255) / 256;

    // 1) weight split into fragment table (once, tiny)
    wsplit_kernel<<<480, 256>>>(W1, W2, W3, mw1);
    // 2) zero degrees
    zero_deg_kernel<<<(N + 255) / 256, 256>>>(N);
    // 3) histogram
    hist_kernel<<<(E + 255) / 256, 256>>>(ei, E);
    // 4) layer-1 GEMM  <-- profiled slot
    gemm_bf_kernel<0, 0><<<g256, 256>>>(x, FW1, 4, N, 32);
    // 5) scan
    scan_kernel<<<1, 1024>>>(N);
    // 6) scatter
    scatter_kernel<<<(E + 255) / 256, 256>>>(ei, E);
    // layer-1 attention + aggregation
    al_kernel<<<alBlocks4, 256>>>(a1s, a1d, N, 4, 64);
    agg_kernel<4, 64><<<N, 128>>>(b1, 1);

    // ---- layer 2 ----
    gemm_bf_kernel<1, 0><<<g256, 256>>>(x, FW2, 4, N, 256);
    al_kernel<<<alBlocks4, 256>>>(a2s, a2d, N, 4, 64);
    agg_kernel<4, 64><<<N, 128>>>(b2, 1);

    // ---- layer 3 ----
    gemm_bf_kernel<1, 0><<<g128, 256>>>(x, FW3, 2, N, 256);
    al_kernel<<<alBlocks1, 256>>>(a3s, a3d, N, 1, 128);
    agg_kernel<1, 128><<<N, 64>>>(b3, 0);

    // ---- edge MLP precompute (single combined GEMM) ----
    gemm_bf_kernel<1, 1><<<g128, 256>>>(x, FPC, 2, N, 128);

    // ---- edge MLP ----
    int blocks = (E + 31) / 32;
    edge_mlp_kernel<<<blocks, 1024>>>(ei, ea, mw1, mb1, mw2, mb2, mw3, mb3, out, E);
}

// round 11
// speedup vs baseline: 1.8317x; 1.1473x over previous
#include <cuda_runtime.h>
#include <cuda_bf16.h>
#include <math.h>

// ---------------- problem constants ----------------
#define MAXN 50000
#define MAXE 800000
#define D12  256

// ---------------- scratch (device globals, compile-time symbol refs only) ---
__device__ float g_bufA[MAXN * D12];       // h (post-GEMM)
__device__ float g_bufB[MAXN * D12];       // aggregated output
__device__ unsigned g_Wf[122880];          // precomputed bf16 B-fragment table
__device__ float g_als[MAXN * 4];
__device__ float g_ald[MAXN * 4];
__device__ float g_pcomb[MAXN * 128];      // [prow | pcol] combined
__device__ int g_deg[MAXN];
__device__ int g_off[MAXN + 1];
__device__ int g_cur[MAXN];
__device__ int g_csr[MAXE];

// fragment-table offsets (words)
#define FW1   0        // 32*256   = 8192   (nBn=4, K=32)
#define FW2   8192     // 256*256  = 65536  (nBn=4, K=256)
#define FW3   73728    // 256*128  = 32768  (nBn=2, K=256)
#define FPC   106496   // 128*128  = 16384  (nBn=2, K=128, block-structured mw1)

__device__ __forceinline__ unsigned pack_bf16(float lo, float hi) {
    unsigned d;
    asm("cvt.rn.bf16x2.f32 %0, %1, %2;" : "=r"(d) : "f"(hi), "f"(lo));
    return d;
}

// ---------------- one-time weight split into mma fragment layout -----------
__global__ void wsplit_kernel(const float* W1, const float* W2, const float* W3,
                              const float* mw1) {
    int w = blockIdx.x * blockDim.x + threadIdx.x;
    if (w >= 122880) return;
    const float* src;
    int srcNc, nBn, rel, pcMode;
    if (w < 8192)        { src = W1;  srcNc = 256; nBn = 4; rel = w;          pcMode = 0; }
    else if (w < 73728)  { src = W2;  srcNc = 256; nBn = 4; rel = w - 8192;   pcMode = 0; }
    else if (w < 106496) { src = W3;  srcNc = 128; nBn = 2; rel = w - 73728;  pcMode = 0; }
    else                 { src = mw1; srcNc = 64;  nBn = 2; rel = w - 106496; pcMode = 1; }
    int tile = rel >> 10;
    int r = rel & 1023;
    int ni = r >> 7;
    int lane = (r >> 2) & 31;
    int sub = r & 3;
    int bs = sub >> 1, bw = sub & 1;
    int g = lane >> 2, tg = lane & 3;
    int bn = tile % nBn, t = tile / nBn;
    int P = tg + bw * 4;
    int colWithin = ni * 8 + g;
    int col = pcMode ? colWithin : (bn * 64 + colWithin);
    int k = (pcMode ? bn * 128 : 0) + t * 16 + 2 * P;
    float x0 = src[k * srcNc + col];
    float x1 = src[(k + 1) * srcNc + col];
    unsigned big = pack_bf16(x0, x1);
    float lo = __uint_as_float(big << 16);
    float hi = __uint_as_float(big & 0xffff0000u);
    unsigned sml = pack_bf16(x0 - lo, x1 - hi);
    g_Wf[w] = bs ? sml : big;
}

// ---------------- CSR construction ----------------
__global__ void zero_deg_kernel(int n) {
    int i = blockIdx.x * blockDim.x + threadIdx.x;
    if (i < n) g_deg[i] = 0;
}

__global__ void hist_kernel(const int* ei, int E) {
    int i = blockIdx.x * blockDim.x + threadIdx.x;
    if (i < E) atomicAdd(&g_deg[ei[E + i]], 1);
}

// warp-shuffle block scan: 1024 threads, each owns a contiguous run.
__global__ void scan_kernel(int n) {
    __shared__ int warpsum[32];
    int tid = threadIdx.x;
    int per = (n + 1023) >> 10;
    int start = tid * per;
    int end = min(start + per, n);
    int s = 0;
    for (int i = start; i < end; i++) s += g_deg[i];

    int lane = tid & 31, wid = tid >> 5;
    int incl = s;
#pragma unroll
    for (int o = 1; o < 32; o <<= 1) {
        int v = __shfl_up_sync(0xffffffffu, incl, o);
        if (lane >= o) incl += v;
    }
    if (lane == 31) warpsum[wid] = incl;
    __syncthreads();
    if (wid == 0) {
        int w = warpsum[lane];
        int wi = w;
#pragma unroll
        for (int o = 1; o < 32; o <<= 1) {
            int v = __shfl_up_sync(0xffffffffu, wi, o);
            if (lane >= o) wi += v;
        }
        warpsum[lane] = wi - w;   // exclusive warp prefix
    }
    __syncthreads();
    int run = (incl - s) + warpsum[wid];   // exclusive prefix for this thread
    for (int i = start; i < end; i++) {
        int d = g_deg[i];
        g_off[i] = run;
        g_cur[i] = run;
        run += d;
    }
    if (tid == 1023) g_off[n] = run;
}

__global__ void scatter_kernel(const int* ei, int E) {
    int i = blockIdx.x * blockDim.x + threadIdx.x;
    if (i < E) {
        int d = ei[E + i];
        int s = ei[i];
        int p = atomicAdd(&g_cur[d], 1);
        g_csr[p] = s;
    }
}

// ---------------- 3-term bf16 tensor-core GEMM (double-buffered A) ---------
__device__ __forceinline__ void mma_bf16(float& d0, float& d1, float& d2, float& d3,
                                         unsigned a0, unsigned a1, unsigned a2, unsigned a3,
                                         unsigned b0, unsigned b1) {
    asm volatile(
        "mma.sync.aligned.m16n8k16.row.col.f32.bf16.bf16.f32 "
        "{%0,%1,%2,%3}, {%4,%5,%6,%7}, {%8,%9}, {%0,%1,%2,%3};"
        : "+f"(d0), "+f"(d1), "+f"(d2), "+f"(d3)
        : "r"(a0), "r"(a1), "r"(a2), "r"(a3), "r"(b0), "r"(b1));
}

template <int ASRC, int CSEL>
__global__ void __launch_bounds__(256) gemm_bf_kernel(const float* Aext, int fbase,
                                                      int nBn, int M, int K) {
    const float* A;
    if constexpr (ASRC == 0) A = Aext; else A = (const float*)g_bufB;
    float* C;
    if constexpr (CSEL == 0) C = g_bufA; else C = g_pcomb;
    int Nc = nBn * 64;

    __shared__ unsigned sAb[2][1024];
    __shared__ unsigned sAs[2][1024];

    int tid = threadIdx.x;
    int bm = blockIdx.y * 128;
    int bn = blockIdx.x;
    int warpId = tid >> 5;
    int lane = tid & 31;
    int g = lane >> 2;
    int tg = lane & 3;
    int wCol = (warpId >> 2) * 32;
    int wTile0 = (warpId & 3) * 2;

    int ar = tid >> 1;
    int khalf = tid & 1;
    int att = ar >> 4;
    int asub = ar & 15;
    int ahi = asub >> 3;
    int agg = asub & 7;

    float d[2][4][4];
#pragma unroll
    for (int mi = 0; mi < 2; mi++)
#pragma unroll
        for (int ni = 0; ni < 4; ni++)
#pragma unroll
            for (int q = 0; q < 4; q++) d[mi][ni][q] = 0.f;

    const unsigned* Wf = (const unsigned*)g_Wf;
    int p = 0;

    for (int k0 = 0; k0 < K; k0 += 16, p ^= 1) {
        int t = k0 >> 4;
        uint4 bfr[4];
        {
            const uint4* fb = (const uint4*)(Wf + fbase + (size_t)(t * nBn + bn) * 1024);
#pragma unroll
            for (int nj = 0; nj < 4; nj++)
                bfr[nj] = fb[((wCol >> 3) + nj) * 32 + lane];
        }
        {
            float4 v0 = make_float4(0.f, 0.f, 0.f, 0.f);
            float4 v1 = make_float4(0.f, 0.f, 0.f, 0.f);
            if (bm + ar < M) {
                const float* pp = A + (size_t)(bm + ar) * K + k0 + khalf * 8;
                v0 = *(const float4*)pp;
                v1 = *(const float4*)(pp + 4);
            }
            float xs[8] = {v0.x, v0.y, v0.z, v0.w, v1.x, v1.y, v1.z, v1.w};
#pragma unroll
            for (int p2 = 0; p2 < 4; p2++) {
                int wsl = khalf * 2 + ahi;
                int slot = p2 ^ ((agg >> 1) & 3);
                int idx = att * 128 + (agg * 4 + slot) * 4 + wsl;
                unsigned big = pack_bf16(xs[2 * p2], xs[2 * p2 + 1]);
                float lo = __uint_as_float(big << 16);
                float hi = __uint_as_float(big & 0xffff0000u);
                sAb[p][idx] = big;
                sAs[p][idx] = pack_bf16(xs[2 * p2] - lo, xs[2 * p2 + 1] - hi);
            }
        }
        __syncthreads();

        uint4 afb[2], afs[2];
#pragma unroll
        for (int mi = 0; mi < 2; mi++) {
            int base = (wTile0 + mi) * 128 + (g * 4 + (tg ^ ((g >> 1) & 3))) * 4;
            afb[mi] = *(const uint4*)&sAb[p][base];
            afs[mi] = *(const uint4*)&sAs[p][base];
        }

#pragma unroll
        for (int ni = 0; ni < 4; ni++) {
            uint4 b = bfr[ni];
#pragma unroll
            for (int mi = 0; mi < 2; mi++) {
                float* dd = d[mi][ni];
                mma_bf16(dd[0], dd[1], dd[2], dd[3],
                         afb[mi].x, afb[mi].y, afb[mi].z, afb[mi].w, b.x, b.y);
                mma_bf16(dd[0], dd[1], dd[2], dd[3],
                         afb[mi].x, afb[mi].y, afb[mi].z, afb[mi].w, b.z, b.w);
                mma_bf16(dd[0], dd[1], dd[2], dd[3],
                         afs[mi].x, afs[mi].y, afs[mi].z, afs[mi].w, b.x, b.y);
            }
        }
    }

#pragma unroll
    for (int mi = 0; mi < 2; mi++) {
#pragma unroll
        for (int ni = 0; ni < 4; ni++) {
            int row0 = bm + (wTile0 + mi) * 16 + g;
            int col = bn * 64 + wCol + ni * 8 + tg * 2;
            if (row0 < M)
                *(float2*)(C + (size_t)row0 * Nc + col) = make_float2(d[mi][ni][0], d[mi][ni][1]);
            if (row0 + 8 < M)
                *(float2*)(C + (size_t)(row0 + 8) * Nc + col) = make_float2(d[mi][ni][2], d[mi][ni][3]);
        }
    }
}

// ---------------- per-node attention coefficients ----------------
__global__ void al_kernel(const float* as, const float* ad, int N, int H, int C) {
    int gw = (blockIdx.x * blockDim.x + threadIdx.x) >> 5;
    int lane = threadIdx.x & 31;
    int n = gw / H;
    int hd = gw % H;
    if (n >= N) return;
    size_t base = (size_t)n * H * C + (size_t)hd * C;
    float s1 = 0.f, s2 = 0.f;
    for (int c = lane; c < C; c += 32) {
        float v = g_bufA[base + c];
        s1 = fmaf(v, as[hd * C + c], s1);
        s2 = fmaf(v, ad[hd * C + c], s2);
    }
#pragma unroll
    for (int o = 16; o; o >>= 1) {
        s1 += __shfl_down_sync(0xffffffffu, s1, o);
        s2 += __shfl_down_sync(0xffffffffu, s2, o);
    }
    if (lane == 0) {
        g_als[n * H + hd] = s1;
        g_ald[n * H + hd] = s2;
    }
}

// ---------------- GAT aggregation, float2-vectorized: bufA -> bufB ---------
template <int H, int C>
__global__ void agg_kernel(const float* bias, int applyElu) {
    const int D2 = H * C / 2;
    const int CHUNK = (H == 4) ? 32 : 64;
    int n = blockIdx.x;
    int t = threadIdx.x;
    __shared__ float sh_m[H];
    __shared__ float sh_iz[H];
    __shared__ float sh_ad[H];
    __shared__ float sh_alpha[CHUNK * H];
    __shared__ int sh_src[CHUNK];

    int o0 = g_off[n];
    int deg = g_off[n + 1] - o0;
    int wid = t >> 5, lane = t & 31;

    if (wid < H) {
        int hd = wid;
        float adn = g_ald[n * H + hd];
        float m = -1e30f, s = 0.f;
        for (int j = lane; j <= deg; j += 32) {
            int src = (j < deg) ? g_csr[o0 + j] : n;
            float att = g_als[src * H + hd] + adn;
            att = att > 0.f ? att : 0.2f * att;
            float mn = fmaxf(m, att);
            s = s * __expf(m - mn) + __expf(att - mn);
            m = mn;
        }
#pragma unroll
        for (int o = 16; o; o >>= 1) {
            float m2 = __shfl_down_sync(0xffffffffu, m, o);
            float s2 = __shfl_down_sync(0xffffffffu, s, o);
            float mn = fmaxf(m, m2);
            s = s * __expf(m - mn) + s2 * __expf(m2 - mn);
            m = mn;
        }
        if (lane == 0) {
            sh_m[hd] = m;
            sh_iz[hd] = 1.0f / s;
            sh_ad[hd] = adn;
        }
    }
    __syncthreads();

    int head = t / (C / 2);
    float2 acc = make_float2(0.f, 0.f);
    int total = deg + 1;
    const float2* h2 = (const float2*)g_bufA;
    for (int base = 0; base < total; base += CHUNK) {
        int cnt = min(CHUNK, total - base);
        {
            int j = t / H;
            int hd = t % H;
            if (j < cnt) {
                int src = (base + j < deg) ? g_csr[o0 + base + j] : n;
                if (hd == 0) sh_src[j] = src;
                float att = g_als[src * H + hd] + sh_ad[hd];
                att = att > 0.f ? att : 0.2f * att;
                sh_alpha[j * H + hd] = __expf(att - sh_m[hd]) * sh_iz[hd];
            }
        }
        __syncthreads();
#pragma unroll 4
        for (int j = 0; j < cnt; j++) {
            float2 v = h2[(size_t)sh_src[j] * D2 + t];
            float a = sh_alpha[j * H + head];
            acc.x = fmaf(v.x, a, acc.x);
            acc.y = fmaf(v.y, a, acc.y);
        }
        __syncthreads();
    }
    float rx = acc.x + bias[2 * t];
    float ry = acc.y + bias[2 * t + 1];
    if (applyElu) {
        rx = rx > 0.f ? rx : expm1f(rx);
        ry = ry > 0.f ? ry : expm1f(ry);
    }
    *(float2*)(g_bufB + (size_t)n * (2 * D2) + 2 * t) = make_float2(rx, ry);
}

// ---------------- edge MLP: 2 edges per warp, float2-packed sw2 ------------
__global__ void __launch_bounds__(1024) edge_mlp_kernel(const int* ei, const float* ea,
                                const float* mw1, const float* mb1,
                                const float* mw2, const float* mb2,
                                const float* mw3, const float* mb3,
                                float* out, int E) {
    __shared__ float2 sw2t[1024];   // sw2t[sl*32+lane] = (mw2[2sl][lane], mw2[2sl+1][lane])
    int tid = threadIdx.x;
    {
        int sl = tid >> 5, ln = tid & 31;
        sw2t[tid] = make_float2(mw2[sl * 64 + ln], mw2[sl * 64 + 32 + ln]);
    }
    __syncthreads();

    int warp = (int)((blockIdx.x * (size_t)blockDim.x + tid) >> 5);
    int lane = tid & 31;
    int e0 = warp * 2;
    if (e0 >= E) return;
    bool has2 = (e0 + 1 < E);
    int e1 = has2 ? e0 + 1 : e0;

    int rowA = ei[e0], colA = ei[E + e0];
    int rowB = ei[e1], colB = ei[E + e1];
    float eaA0 = ea[e0 * 2], eaA1 = ea[e0 * 2 + 1];
    float eaB0 = ea[e1 * 2], eaB1 = ea[e1 * 2 + 1];

    int j0 = lane * 2;
    float w1e0 = mw1[256 * 64 + j0], w1e0b = mw1[256 * 64 + j0 + 1];
    float w1e1 = mw1[257 * 64 + j0], w1e1b = mw1[257 * 64 + j0 + 1];
    float bj0 = mb1[j0], bj1 = mb1[j0 + 1];

    float2 prA = *(const float2*)(g_pcomb + (size_t)rowA * 128 + j0);
    float2 pcA = *(const float2*)(g_pcomb + (size_t)colA * 128 + 64 + j0);
    float2 prB = *(const float2*)(g_pcomb + (size_t)rowB * 128 + j0);
    float2 pcB = *(const float2*)(g_pcomb + (size_t)colB * 128 + 64 + j0);

    float o1aA = fmaxf(prA.x + pcA.x + eaA0 * w1e0 + eaA1 * w1e1 + bj0, 0.f);
    float o1bA = fmaxf(prA.y + pcA.y + eaA0 * w1e0b + eaA1 * w1e1b + bj1, 0.f);
    float o1aB = fmaxf(prB.x + pcB.x + eaB0 * w1e0 + eaB1 * w1e1 + bj0, 0.f);
    float o1bB = fmaxf(prB.y + pcB.y + eaB0 * w1e0b + eaB1 * w1e1b + bj1, 0.f);

    float accA = mb2[lane];
    float accB = accA;
#pragma unroll
    for (int sl = 0; sl < 32; sl++) {
        float2 w = sw2t[sl * 32 + lane];
        float vaA = __shfl_sync(0xffffffffu, o1aA, sl);
        float vbA = __shfl_sync(0xffffffffu, o1bA, sl);
        float vaB = __shfl_sync(0xffffffffu, o1aB, sl);
        float vbB = __shfl_sync(0xffffffffu, o1bB, sl);
        accA = fmaf(vaA, w.x, accA);
        accA = fmaf(vbA, w.y, accA);
        accB = fmaf(vaB, w.x, accB);
        accB = fmaf(vbB, w.y, accB);
    }
    accA = fmaxf(accA, 0.f);
    accB = fmaxf(accB, 0.f);

    float w3 = mw3[lane];
    float vA = accA * w3;
    float vB = accB * w3;
#pragma unroll
    for (int o = 16; o; o >>= 1) {
        vA += __shfl_down_sync(0xffffffffu, vA, o);
        vB += __shfl_down_sync(0xffffffffu, vB, o);
    }
    if (lane == 0) {
        out[e0] = vA + mb3[0];
        if (has2) out[e0 + 1] = vB + mb3[0];
    }
}

// ---------------- launch ----------------
extern "C" void kernel_launch(void* const* d_in, const int* in_sizes, int n_in,
                              void* d_out, int out_size) {
    const float* x = (const float*)d_in[0];
    const int* ei = (const int*)d_in[1];
    const float* ea = (const float*)d_in[2];
    const float* W1 = (const float*)d_in[3];
    const float* a1s = (const float*)d_in[4];
    const float* a1d = (const float*)d_in[5];
    const float* b1 = (const float*)d_in[6];
    const float* W2 = (const float*)d_in[7];
    const float* a2s = (const float*)d_in[8];
    const float* a2d = (const float*)d_in[9];
    const float* b2 = (const float*)d_in[10];
    const float* W3 = (const float*)d_in[11];
    const float* a3s = (const float*)d_in[12];
    const float* a3d = (const float*)d_in[13];
    const float* b3 = (const float*)d_in[14];
    const float* mw1 = (const float*)d_in[15];
    const float* mb1 = (const float*)d_in[16];
    const float* mw2 = (const float*)d_in[17];
    const float* mb2 = (const float*)d_in[18];
    const float* mw3 = (const float*)d_in[19];
    const float* mb3 = (const float*)d_in[20];
    float* out = (float*)d_out;

    int N = in_sizes[0] / 32;
    int E = in_sizes[1] / 2;

    int mBlocks = (N + 127) / 128;
    dim3 g256(4, mBlocks);
    dim3 g128(2, mBlocks);
    int alBlocks4 = ((N * 4) * 32 + 255) / 256;
    int alBlocks1 = ((N * 1) * 32 + 255) / 256;

    // 1) weight split into fragment table (once, tiny)
    wsplit_kernel<<<480, 256>>>(W1, W2, W3, mw1);
    // 2) zero degrees
    zero_deg_kernel<<<(N + 255) / 256, 256>>>(N);
    // 3) histogram
    hist_kernel<<<(E + 255) / 256, 256>>>(ei, E);
    // 4) layer-1 GEMM  <-- profiled slot (control)
    gemm_bf_kernel<0, 0><<<g256, 256>>>(x, FW1, 4, N, 32);
    // 5) scan (warp-shuffle version)
    scan_kernel<<<1, 1024>>>(N);
    // 6) scatter
    scatter_kernel<<<(E + 255) / 256, 256>>>(ei, E);
    // layer-1 attention + aggregation
    al_kernel<<<alBlocks4, 256>>>(a1s, a1d, N, 4, 64);
    agg_kernel<4, 64><<<N, 128>>>(b1, 1);

    // ---- layer 2 ----
    gemm_bf_kernel<1, 0><<<g256, 256>>>(x, FW2, 4, N, 256);
    al_kernel<<<alBlocks4, 256>>>(a2s, a2d, N, 4, 64);
    agg_kernel<4, 64><<<N, 128>>>(b2, 1);

    // ---- layer 3 ----
    gemm_bf_kernel<1, 0><<<g128, 256>>>(x, FW3, 2, N, 256);
    al_kernel<<<alBlocks1, 256>>>(a3s, a3d, N, 1, 128);
    agg_kernel<1, 128><<<N, 64>>>(b3, 0);

    // ---- edge MLP precompute (single combined GEMM) ----
    gemm_bf_kernel<1, 1><<<g128, 256>>>(x, FPC, 2, N, 128);

    // ---- edge MLP (2 edges per warp) ----
    int blocks = (E + 63) / 64;
    edge_mlp_kernel<<<blocks, 1024>>>(ei, ea, mw1, mb1, mw2, mb2, mw3, mb3, out, E);
}